// round 13
// baseline (speedup 1.0000x reference)
#include <cuda_runtime.h>
#include <cuda_fp16.h>
#include <math_constants.h>
#include <cstdint>

// ---------------------------------------------------------------------------
// Problem constants
// ---------------------------------------------------------------------------
#define B_ 8
#define S_ 2048
#define D_ 1024

typedef __half fp16;

// ---------------------------------------------------------------------------
// Scratch (device globals; allocation-free rule)
// ---------------------------------------------------------------------------
__device__ fp16 gXq[B_*S_*D_], gXk[B_*S_*D_], gXv[B_*S_*D_];
__device__ fp16 gWq[D_*D_], gWk[D_*D_], gWv[D_*D_];
__device__ fp16 gQ[B_*S_*D_], gK[B_*S_*D_], gV[B_*S_*D_];
__device__ fp16 gVt[B_*S_*D_];                // [B][D][S]
__device__ float gScores[B_*S_*S_];
__device__ fp16 gP[(long long)B_*S_*S_];

// ---------------------------------------------------------------------------
// PTX helpers (sm_80-baseline: cp.async, ldmatrix, mma.sync)
// ---------------------------------------------------------------------------
__device__ __forceinline__ uint32_t smem_u32(const void* p) {
    uint32_t a;
    asm("{ .reg .u64 t; cvta.to.shared.u64 t, %1; cvt.u32.u64 %0, t; }" : "=r"(a) : "l"(p));
    return a;
}
__device__ __forceinline__ void cp16(uint32_t dst, const void* src) {
    asm volatile("cp.async.cg.shared.global [%0], [%1], 16;"
                 :: "r"(dst), "l"(__cvta_generic_to_global(src)) : "memory");
}
#define CP_COMMIT() asm volatile("cp.async.commit_group;" ::: "memory")
#define CP_WAIT(n)  asm volatile("cp.async.wait_group %0;" :: "n"(n) : "memory")

__device__ __forceinline__ void ldm_x4(uint32_t* r, uint32_t addr) {
    asm volatile("ldmatrix.sync.aligned.m8n8.x4.shared.b16 {%0,%1,%2,%3}, [%4];"
                 : "=r"(r[0]), "=r"(r[1]), "=r"(r[2]), "=r"(r[3]) : "r"(addr));
}
__device__ __forceinline__ void mma_fp16(float* d, const uint32_t* a, const uint32_t* b) {
    asm volatile("mma.sync.aligned.m16n8k16.row.col.f32.f16.f16.f32 "
                 "{%0,%1,%2,%3}, {%4,%5,%6,%7}, {%8,%9}, {%0,%1,%2,%3};"
                 : "+f"(d[0]), "+f"(d[1]), "+f"(d[2]), "+f"(d[3])
                 : "r"(a[0]), "r"(a[1]), "r"(a[2]), "r"(a[3]), "r"(b[0]), "r"(b[1]));
}

// ---------------------------------------------------------------------------
// GEMM: C[M,N] = A[M,K] * B[N,K]^T, single-pass fp16, mma.sync
// CTA tile 128(M) x 256(N), BK=32, 8 warps (2m x 4n, each 64x64),
// 4-stage cp.async, register-level fragment double buffering.
// SMEM rows: 32 fp16 = 64B at 80B stride (conflict-free ldmatrix).
// EPI==0: fp32 store of acc. EPI==1: fp16 store of acc+bias.
// ---------------------------------------------------------------------------
#define BK_ 32
#define ROWB 80
#define A_MATB (128 * ROWB)          // 10240
#define B_MATB (256 * ROWB)          // 20480
#define STAGEB (A_MATB + B_MATB)     // 30720
#define NSTAGE 4
#define SMEM_DYN (NSTAGE * STAGEB)   // 122880 -> 1 CTA/SM (8 warps)
#define NTHREADS 256

struct Frag {
    uint32_t a[4][4];
    uint32_t b[8][2];
};

__device__ __forceinline__ void load_stage(uint32_t sbase, int slot, int tid,
                                           const fp16* A, const fp16* Bm,
                                           int bm, int bn, int K, int k0)
{
    uint32_t sb = sbase + (uint32_t)slot * STAGEB;
#pragma unroll
    for (int t = 0; t < 6; t++) {
        int u = tid + NTHREADS * t;         // 0..1535
        int row = u >> 2;                   // 0..383
        int c = (u & 3) * 16;               // byte offset within 64B row
        if (row < 128) {
            uint32_t so = (uint32_t)(row * ROWB + c);
            size_t gA = (size_t)(bm + row) * K + k0 + (c >> 1);
            cp16(sb + so, A + gA);
        } else {
            int br = row - 128;             // 0..255
            uint32_t so = (uint32_t)(A_MATB + br * ROWB + c);
            size_t gB = (size_t)(bn + br) * K + k0 + (c >> 1);
            cp16(sb + so, Bm + gB);
        }
    }
    CP_COMMIT();
}

__device__ __forceinline__ void load_frags(Frag& f, uint32_t st, int kb,
                                           int wm, int wn,
                                           int a_row, int a_k16,
                                           int b_row, int b_k16)
{
#pragma unroll
    for (int mf = 0; mf < 4; mf++) {
        uint32_t ra = st + (uint32_t)((wm + mf * 16 + a_row) * ROWB + kb + a_k16);
        ldm_x4(f.a[mf], ra);
    }
#pragma unroll
    for (int np = 0; np < 4; np++) {
        uint32_t rb = st + A_MATB +
                      (uint32_t)((wn + np * 16 + b_row) * ROWB + kb + b_k16);
        uint32_t th[4];
        ldm_x4(th, rb);
        f.b[np*2][0]   = th[0]; f.b[np*2][1]   = th[1];
        f.b[np*2+1][0] = th[2]; f.b[np*2+1][1] = th[3];
    }
}

__device__ __forceinline__ void run_mmas(float acc[4][8][4], const Frag& f)
{
#pragma unroll
    for (int mf = 0; mf < 4; mf++)
#pragma unroll
        for (int nf = 0; nf < 8; nf++)
            mma_fp16(acc[mf][nf], f.a[mf], f.b[nf]);
}

template <int EPI>
__global__ __launch_bounds__(NTHREADS, 1)
void mma_gemm(const fp16* __restrict__ A, const fp16* __restrict__ Bm,
              const float* __restrict__ bias,
              float* __restrict__ Cf, fp16* __restrict__ Ch,
              int M, int N, int K,
              long long sA, long long sB, long long sC)
{
    extern __shared__ char smem[];
    const int tid  = threadIdx.x;
    const int wid  = tid >> 5;              // 0..7
    const int lane = tid & 31;

    const int bz = blockIdx.z;
    A  += (long long)bz * sA;
    Bm += (long long)bz * sB;

    const int bm = blockIdx.y * 128;
    const int bn = blockIdx.x * 256;
    const int wm = (wid >> 2) * 64;         // 2 warps along M
    const int wn = (wid & 3) * 64;          // 4 warps along N

    const uint32_t sbase = smem_u32(smem);

    float acc[4][8][4];
#pragma unroll
    for (int i = 0; i < 4; i++)
#pragma unroll
        for (int j = 0; j < 8; j++)
#pragma unroll
            for (int q = 0; q < 4; q++) acc[i][j][q] = 0.f;

    const int NITER = K / BK_;

    load_stage(sbase, 0, tid, A, Bm, bm, bn, K, 0);
    load_stage(sbase, 1, tid, A, Bm, bm, bn, K, BK_);
    load_stage(sbase, 2, tid, A, Bm, bm, bn, K, 2 * BK_);

    const int a_row = lane & 15;
    const int a_k16 = (lane >> 4) * 16;
    const int b_row = (lane & 7) + ((lane >> 4) << 3);
    const int b_k16 = ((lane >> 3) & 1) * 16;

    Frag f0, f1;

    // wait stage 0, preload fragments ks=0
    CP_WAIT(2);
    __syncthreads();
    load_frags(f0, sbase, 0, wm, wn, a_row, a_k16, b_row, b_k16);

    for (int i = 0; i < NITER; i++) {
        uint32_t st = sbase + (uint32_t)(i & 3) * STAGEB;

        // prefetch fragments for ks=1 of this stage, then MMA ks=0
        load_frags(f1, st, 32, wm, wn, a_row, a_k16, b_row, b_k16);
        run_mmas(acc, f0);

        // issue global loads for stage i+3
        if (i + 3 < NITER)
            load_stage(sbase, (i + 3) & 3, tid, A, Bm, bm, bn, K, (i + 3) * BK_);

        // make stage i+1 visible, prefetch its ks=0 fragments
        if (i + 1 < NITER) {
            if (i + 4 <= NITER)      CP_WAIT(2);
            else if (i + 3 == NITER) CP_WAIT(1);
            else                     CP_WAIT(0);
            __syncthreads();
            uint32_t stn = sbase + (uint32_t)((i + 1) & 3) * STAGEB;
            load_frags(f0, stn, 0, wm, wn, a_row, a_k16, b_row, b_k16);
        }

        // MMA ks=1 (overlaps with the f0 ldmatrix latency above)
        run_mmas(acc, f1);
    }

    // ---- epilogue (register -> global) ----
    const int rr = lane >> 2;
    const int cc = (lane & 3) * 2;
#pragma unroll
    for (int mf = 0; mf < 4; mf++) {
#pragma unroll
        for (int nf = 0; nf < 8; nf++) {
            const int row = bm + wm + mf * 16 + rr;
            const int col = bn + wn + nf * 8 + cc;
            float* a4 = acc[mf][nf];
            if (EPI == 0) {
                float* dst = Cf + (long long)bz * sC;
                *(float2*)&dst[(size_t)row * N + col]       = make_float2(a4[0], a4[1]);
                *(float2*)&dst[(size_t)(row + 8) * N + col] = make_float2(a4[2], a4[3]);
            } else {
                float b0 = bias[col], b1 = bias[col + 1];
                __half2 p0; p0.x = __float2half_rn(a4[0] + b0); p0.y = __float2half_rn(a4[1] + b1);
                __half2 p1; p1.x = __float2half_rn(a4[2] + b0); p1.y = __float2half_rn(a4[3] + b1);
                *(__half2*)&Ch[(size_t)row * N + col]       = p0;
                *(__half2*)&Ch[(size_t)(row + 8) * N + col] = p1;
            }
        }
    }
}

// ---------------------------------------------------------------------------
// Prep: round three fp32 tensors -> fp16 (one launch for X's, one for W's)
// ---------------------------------------------------------------------------
__global__ __launch_bounds__(256)
void round3_kernel(const float4* __restrict__ a, const float4* __restrict__ b,
                   const float4* __restrict__ c,
                   uint2* __restrict__ oa, uint2* __restrict__ ob,
                   uint2* __restrict__ oc, int blk_per)
{
    int bb = blockIdx.x;
    const float4* src; uint2* dst;
    if (bb < blk_per)            { src = a; dst = oa; }
    else if (bb < 2 * blk_per)   { src = b; dst = ob; bb -= blk_per; }
    else                         { src = c; dst = oc; bb -= 2 * blk_per; }
    int i = bb * 256 + threadIdx.x;
    float4 x = src[i];
    __align__(8) fp16 h[4];
    h[0] = __float2half_rn(x.x); h[1] = __float2half_rn(x.y);
    h[2] = __float2half_rn(x.z); h[3] = __float2half_rn(x.w);
    dst[i] = *(uint2*)h;
}
#define XBLK (B_ * S_ * D_ / 4 / 256)      // 16384
#define WBLK (D_ * D_ / 4 / 256)           // 1024

// ---------------------------------------------------------------------------
// per-batch transpose of V: [B][S][D] -> [B][D][S]
// ---------------------------------------------------------------------------
__global__ __launch_bounds__(256)
void transpose_kernel(const fp16* __restrict__ src, fp16* __restrict__ dst)
{
    __shared__ fp16 t[32][33];
    const int b = blockIdx.z;
    const int x0 = blockIdx.x * 32;   // D dim
    const int y0 = blockIdx.y * 32;   // S dim
    const int tx = threadIdx.x & 31;
    const int ty = threadIdx.x >> 5;  // 0..7
    const fp16* s = src + (size_t)b * S_ * D_;
    fp16* d = dst + (size_t)b * S_ * D_;
#pragma unroll
    for (int j = 0; j < 4; j++) {
        int r = ty + j * 8;
        t[r][tx] = s[(size_t)(y0 + r) * D_ + x0 + tx];
    }
    __syncthreads();
#pragma unroll
    for (int j = 0; j < 4; j++) {
        int r = ty + j * 8;
        d[(size_t)(x0 + r) * S_ + y0 + tx] = t[tx][r];
    }
}

// ---------------------------------------------------------------------------
// Masked softmax: fp32 raw scores (unscaled) -> fp16 prob row; applies 1/32.
// ---------------------------------------------------------------------------
__global__ __launch_bounds__(256)
void softmax_kernel(const float* __restrict__ scores, const int* __restrict__ mask,
                    fp16* __restrict__ P)
{
    const int row = blockIdx.x;               // 0..B*S-1
    const int b   = row / S_;
    const float* p = scores + (long long)row * S_;
    const int* mrow = mask + (long long)b * S_;

    const int tid = threadIdx.x;
    const int c0 = tid * 8;
    const float sc = 1.0f / 32.0f;            // 1/sqrt(1024)

    float4 v0 = *(const float4*)&p[c0];
    float4 v1 = *(const float4*)&p[c0 + 4];
    int4 m0 = *(const int4*)&mrow[c0];
    int4 m1 = *(const int4*)&mrow[c0 + 4];

    float v[8]  = {v0.x * sc, v0.y * sc, v0.z * sc, v0.w * sc,
                   v1.x * sc, v1.y * sc, v1.z * sc, v1.w * sc};
    int   mk[8] = {m0.x, m0.y, m0.z, m0.w, m1.x, m1.y, m1.z, m1.w};

    float mx = -CUDART_INF_F;
#pragma unroll
    for (int i = 0; i < 8; i++)
        if (mk[i]) mx = fmaxf(mx, v[i]);
#pragma unroll
    for (int o = 16; o > 0; o >>= 1)
        mx = fmaxf(mx, __shfl_xor_sync(0xFFFFFFFFu, mx, o));

    __shared__ float sred[8];
    if ((tid & 31) == 0) sred[tid >> 5] = mx;
    __syncthreads();
    mx = sred[0];
#pragma unroll
    for (int w = 1; w < 8; w++) mx = fmaxf(mx, sred[w]);
    __syncthreads();

    const float mxs = (mx > -CUDART_INF_F) ? mx : 0.f;

    float sum = 0.f;
#pragma unroll
    for (int i = 0; i < 8; i++) {
        float e = mk[i] ? __expf(v[i] - mxs) : 0.f;
        v[i] = e;
        sum += e;
    }
#pragma unroll
    for (int o = 16; o > 0; o >>= 1)
        sum += __shfl_xor_sync(0xFFFFFFFFu, sum, o);
    if ((tid & 31) == 0) sred[tid >> 5] = sum;
    __syncthreads();
    sum = 0.f;
#pragma unroll
    for (int w = 0; w < 8; w++) sum += sred[w];

    const float inv = (sum > 0.f) ? (1.f / sum) : 0.f;

    __align__(16) fp16 hh[8];
#pragma unroll
    for (int i = 0; i < 8; i++)
        hh[i] = __float2half_rn(v[i] * inv);
    *(uint4*)&P[(long long)row * S_ + c0] = *(uint4*)hh;
}

// ---------------------------------------------------------------------------
// Launch
// ---------------------------------------------------------------------------
extern "C" void kernel_launch(void* const* d_in, const int* in_sizes, int n_in,
                              void* d_out, int out_size)
{
    const float* query = (const float*)d_in[0];
    const float* key   = (const float*)d_in[1];
    const float* value = (const float*)d_in[2];
    const int*   mask  = (const int*)  d_in[3];
    const float* Wq    = (const float*)d_in[4];
    const float* bq    = (const float*)d_in[5];
    const float* Wk    = (const float*)d_in[6];
    const float* bk    = (const float*)d_in[7];
    const float* Wv    = (const float*)d_in[8];
    const float* bv    = (const float*)d_in[9];
    float* out = (float*)d_out;

    fp16 *Xq, *Xk, *Xv, *Wqh, *Wkh, *Wvh;
    fp16 *Q, *K, *V, *Vt, *P;
    float* Sc;
    cudaGetSymbolAddress((void**)&Xq,  gXq);
    cudaGetSymbolAddress((void**)&Xk,  gXk);
    cudaGetSymbolAddress((void**)&Xv,  gXv);
    cudaGetSymbolAddress((void**)&Wqh, gWq);
    cudaGetSymbolAddress((void**)&Wkh, gWk);
    cudaGetSymbolAddress((void**)&Wvh, gWv);
    cudaGetSymbolAddress((void**)&Q,   gQ);
    cudaGetSymbolAddress((void**)&K,   gK);
    cudaGetSymbolAddress((void**)&V,   gV);
    cudaGetSymbolAddress((void**)&Vt,  gVt);
    cudaGetSymbolAddress((void**)&P,   gP);
    cudaGetSymbolAddress((void**)&Sc,  gScores);

    cudaFuncSetAttribute(mma_gemm<0>, cudaFuncAttributeMaxDynamicSharedMemorySize, SMEM_DYN);
    cudaFuncSetAttribute(mma_gemm<1>, cudaFuncAttributeMaxDynamicSharedMemorySize, SMEM_DYN);

    const int M = B_ * S_;                  // 16384

    // launch 0: round X inputs to fp16
    round3_kernel<<<3 * XBLK, 256>>>((const float4*)query, (const float4*)key,
                                     (const float4*)value,
                                     (uint2*)Xq, (uint2*)Xk, (uint2*)Xv, XBLK);
    // launch 1: round weights to fp16
    round3_kernel<<<3 * WBLK, 256>>>((const float4*)Wq, (const float4*)Wk,
                                     (const float4*)Wv,
                                     (uint2*)Wqh, (uint2*)Wkh, (uint2*)Wvh, WBLK);

    // launches 2-4: projections (fp16 out, bias in epilogue)
    {
        dim3 g(D_ / 256, M / 128, 1);       // (4, 128)
        mma_gemm<1><<<g, NTHREADS, SMEM_DYN>>>(Xq, Wqh, bq, nullptr, Q, M, D_, D_, 0, 0, 0);
        mma_gemm<1><<<g, NTHREADS, SMEM_DYN>>>(Xk, Wkh, bk, nullptr, K, M, D_, D_, 0, 0, 0);
        mma_gemm<1><<<g, NTHREADS, SMEM_DYN>>>(Xv, Wvh, bv, nullptr, V, M, D_, D_, 0, 0, 0);
    }

    // launch 5 (ncu profiles this): scores = Q K^T per batch, fp32 out
    {
        dim3 g(S_ / 256, S_ / 128, B_);     // (8, 16, 8)
        mma_gemm<0><<<g, NTHREADS, SMEM_DYN>>>(Q, K, nullptr, Sc, nullptr, S_, S_, D_,
                                               (long long)S_ * D_, (long long)S_ * D_,
                                               (long long)S_ * S_);
    }

    // launch 6: transpose V per batch: [S,D] -> [D,S]
    {
        dim3 g(D_ / 32, S_ / 32, B_);
        transpose_kernel<<<g, 256>>>(V, Vt);
    }

    // launch 7: masked softmax (applies 1/sqrt(D)) -> fp16 P
    softmax_kernel<<<B_ * S_, 256>>>(Sc, mask, P);

    // launch 8: out = P V per batch (NT with V^T)
    {
        dim3 g(D_ / 256, S_ / 128, B_);     // (4, 16, 8)
        mma_gemm<0><<<g, NTHREADS, SMEM_DYN>>>(P, Vt, nullptr, out, nullptr, S_, D_, S_,
                                               (long long)S_ * S_, (long long)S_ * D_,
                                               (long long)S_ * D_);
    }
}

// round 14
// speedup vs baseline: 1.0987x; 1.0987x over previous
#include <cuda_runtime.h>
#include <cuda_fp16.h>
#include <math_constants.h>
#include <cstdint>

// ---------------------------------------------------------------------------
// Problem constants
// ---------------------------------------------------------------------------
#define B_ 8
#define S_ 2048
#define D_ 1024

typedef __half fp16;

// ---------------------------------------------------------------------------
// Scratch (device globals; allocation-free rule)
// ---------------------------------------------------------------------------
__device__ fp16 gXq[B_*S_*D_], gXk[B_*S_*D_], gXv[B_*S_*D_];
__device__ fp16 gWq[D_*D_], gWk[D_*D_], gWv[D_*D_];
__device__ fp16 gQ[B_*S_*D_], gK[B_*S_*D_], gV[B_*S_*D_];
__device__ fp16 gVt[B_*S_*D_];                // [B][D][S]
// single buffer: raw fp16 scores, then probs in place
__device__ fp16 gP[(long long)B_*S_*S_];

// ---------------------------------------------------------------------------
// PTX helpers (sm_80-baseline: cp.async, ldmatrix, mma.sync)
// ---------------------------------------------------------------------------
__device__ __forceinline__ uint32_t smem_u32(const void* p) {
    uint32_t a;
    asm("{ .reg .u64 t; cvta.to.shared.u64 t, %1; cvt.u32.u64 %0, t; }" : "=r"(a) : "l"(p));
    return a;
}
__device__ __forceinline__ void cp16(uint32_t dst, const void* src) {
    asm volatile("cp.async.cg.shared.global [%0], [%1], 16;"
                 :: "r"(dst), "l"(__cvta_generic_to_global(src)) : "memory");
}
#define CP_COMMIT() asm volatile("cp.async.commit_group;" ::: "memory")
#define CP_WAIT(n)  asm volatile("cp.async.wait_group %0;" :: "n"(n) : "memory")

__device__ __forceinline__ void ldm_x4(uint32_t* r, uint32_t addr) {
    asm volatile("ldmatrix.sync.aligned.m8n8.x4.shared.b16 {%0,%1,%2,%3}, [%4];"
                 : "=r"(r[0]), "=r"(r[1]), "=r"(r[2]), "=r"(r[3]) : "r"(addr));
}
__device__ __forceinline__ void mma_fp16(float* d, const uint32_t* a, const uint32_t* b) {
    asm volatile("mma.sync.aligned.m16n8k16.row.col.f32.f16.f16.f32 "
                 "{%0,%1,%2,%3}, {%4,%5,%6,%7}, {%8,%9}, {%0,%1,%2,%3};"
                 : "+f"(d[0]), "+f"(d[1]), "+f"(d[2]), "+f"(d[3])
                 : "r"(a[0]), "r"(a[1]), "r"(a[2]), "r"(a[3]), "r"(b[0]), "r"(b[1]));
}

// ---------------------------------------------------------------------------
// GEMM core: C[M,N] = A[M,K] * B[N,K]^T, single-pass fp16, mma.sync
// CTA tile 128x128, BK=32, 4 warps (2m x 2n, each 64x64), 5-stage cp.async,
// register-level fragment double buffering.  2 CTAs/SM.
// EPI==0: fp32 store of acc. EPI==1: fp16 store of acc+bias.
// EPI==2: fp16 store of raw acc (scores).
// ---------------------------------------------------------------------------
#define BK_ 32
#define ROWB 80
#define MATB (128 * ROWB)          // 10240
#define STAGEB (2 * MATB)          // 20480 (A, B)
#define NSTAGE 5
#define SMEM_DYN (NSTAGE * STAGEB) // 102400 -> 2 CTAs/SM
#define NTHREADS 128

struct Frag {
    uint32_t a[4][4];
    uint32_t b[8][2];
};

__device__ __forceinline__ void load_stage(uint32_t sbase, int slot, int tid,
                                           const fp16* A, const fp16* Bm,
                                           int bm, int bn, int K, int k0)
{
    uint32_t sb = sbase + (uint32_t)slot * STAGEB;
#pragma unroll
    for (int t = 0; t < 4; t++) {
        int u = tid + NTHREADS * t;         // 0..511
        int row = u >> 2;                   // 0..127
        int c = (u & 3) * 16;               // byte offset within 64B row
        uint32_t so = (uint32_t)(row * ROWB + c);
        size_t gA = (size_t)(bm + row) * K + k0 + (c >> 1);
        size_t gB = (size_t)(bn + row) * K + k0 + (c >> 1);
        cp16(sb + so,        A  + gA);
        cp16(sb + MATB + so, Bm + gB);
    }
    CP_COMMIT();
}

__device__ __forceinline__ void load_frags(Frag& f, uint32_t st, int kb,
                                           int wm, int wn,
                                           int a_row, int a_k16,
                                           int b_row, int b_k16)
{
#pragma unroll
    for (int mf = 0; mf < 4; mf++) {
        uint32_t ra = st + (uint32_t)((wm + mf * 16 + a_row) * ROWB + kb + a_k16);
        ldm_x4(f.a[mf], ra);
    }
#pragma unroll
    for (int np = 0; np < 4; np++) {
        uint32_t rb = st + MATB +
                      (uint32_t)((wn + np * 16 + b_row) * ROWB + kb + b_k16);
        uint32_t th[4];
        ldm_x4(th, rb);
        f.b[np*2][0]   = th[0]; f.b[np*2][1]   = th[1];
        f.b[np*2+1][0] = th[2]; f.b[np*2+1][1] = th[3];
    }
}

__device__ __forceinline__ void run_mmas(float acc[4][8][4], const Frag& f)
{
#pragma unroll
    for (int mf = 0; mf < 4; mf++)
#pragma unroll
        for (int nf = 0; nf < 8; nf++)
            mma_fp16(acc[mf][nf], f.a[mf], f.b[nf]);
}

template <int EPI>
__device__ __forceinline__ void gemm_core(
    const fp16* __restrict__ A, const fp16* __restrict__ Bm,
    const float* __restrict__ bias,
    float* __restrict__ Cf, fp16* __restrict__ Ch,
    int M, int N, int K, int bm, int bn)
{
    extern __shared__ char smem[];
    const int tid  = threadIdx.x;
    const int wid  = tid >> 5;              // 0..3
    const int lane = tid & 31;

    const int wm = (wid >> 1) * 64;
    const int wn = (wid & 1) * 64;

    const uint32_t sbase = smem_u32(smem);

    float acc[4][8][4];
#pragma unroll
    for (int i = 0; i < 4; i++)
#pragma unroll
        for (int j = 0; j < 8; j++)
#pragma unroll
            for (int q = 0; q < 4; q++) acc[i][j][q] = 0.f;

    const int NITER = K / BK_;

    load_stage(sbase, 0, tid, A, Bm, bm, bn, K, 0);
    load_stage(sbase, 1, tid, A, Bm, bm, bn, K, BK_);
    load_stage(sbase, 2, tid, A, Bm, bm, bn, K, 2 * BK_);
    load_stage(sbase, 3, tid, A, Bm, bm, bn, K, 3 * BK_);

    const int a_row = lane & 15;
    const int a_k16 = (lane >> 4) * 16;
    const int b_row = (lane & 7) + ((lane >> 4) << 3);
    const int b_k16 = ((lane >> 3) & 1) * 16;

    Frag f0, f1;

    // wait stage 0, preload fragments ks=0
    CP_WAIT(3);
    __syncthreads();
    load_frags(f0, sbase, 0, wm, wn, a_row, a_k16, b_row, b_k16);

    for (int i = 0; i < NITER; i++) {
        uint32_t st = sbase + (uint32_t)(i % NSTAGE) * STAGEB;

        // prefetch fragments for ks=1 of this stage, then MMA ks=0
        load_frags(f1, st, 32, wm, wn, a_row, a_k16, b_row, b_k16);
        run_mmas(acc, f0);

        // issue global loads for stage i+4
        if (i + 4 < NITER)
            load_stage(sbase, (i + 4) % NSTAGE, tid, A, Bm, bm, bn, K, (i + 4) * BK_);

        // make stage i+1 visible, prefetch its ks=0 fragments
        if (i + 1 < NITER) {
            if (i + 5 <= NITER)      CP_WAIT(3);
            else if (i + 4 == NITER) CP_WAIT(2);
            else if (i + 3 == NITER) CP_WAIT(1);
            else                     CP_WAIT(0);
            __syncthreads();
            uint32_t stn = sbase + (uint32_t)((i + 1) % NSTAGE) * STAGEB;
            load_frags(f0, stn, 0, wm, wn, a_row, a_k16, b_row, b_k16);
        }

        // MMA ks=1 (overlaps with the f0 ldmatrix latency above)
        run_mmas(acc, f1);
    }

    // ---- epilogue (register -> global) ----
    const int rr = lane >> 2;
    const int cc = (lane & 3) * 2;
#pragma unroll
    for (int mf = 0; mf < 4; mf++) {
#pragma unroll
        for (int nf = 0; nf < 8; nf++) {
            const int row = bm + wm + mf * 16 + rr;
            const int col = bn + wn + nf * 8 + cc;
            float* a4 = acc[mf][nf];
            if (EPI == 0) {
                *(float2*)&Cf[(size_t)row * N + col]       = make_float2(a4[0], a4[1]);
                *(float2*)&Cf[(size_t)(row + 8) * N + col] = make_float2(a4[2], a4[3]);
            } else {
                const float b0 = (EPI == 1) ? bias[col]     : 0.f;
                const float b1 = (EPI == 1) ? bias[col + 1] : 0.f;
                __half2 p0; p0.x = __float2half_rn(a4[0] + b0); p0.y = __float2half_rn(a4[1] + b1);
                __half2 p1; p1.x = __float2half_rn(a4[2] + b0); p1.y = __float2half_rn(a4[3] + b1);
                *(__half2*)&Ch[(size_t)row * N + col]       = p0;
                *(__half2*)&Ch[(size_t)(row + 8) * N + col] = p1;
            }
        }
    }
}

// ---------------------------------------------------------------------------
// Kernel wrappers
// ---------------------------------------------------------------------------
template <int EPI>
__global__ __launch_bounds__(NTHREADS, 2)
void mma_gemm(const fp16* __restrict__ A, const fp16* __restrict__ Bm,
              const float* __restrict__ bias,
              float* __restrict__ Cf, fp16* __restrict__ Ch,
              int M, int N, int K,
              long long sA, long long sB, long long sC)
{
    const long long bz = blockIdx.z;
    gemm_core<EPI>(A + bz * sA, Bm + bz * sB, bias,
                   (EPI == 0) ? (Cf + bz * sC) : nullptr,
                   (EPI == 0) ? nullptr : (Ch + bz * sC),
                   M, N, K, blockIdx.y * 128, blockIdx.x * 128);
}

// fused QKV projections: blockIdx.z selects which projection
__global__ __launch_bounds__(NTHREADS, 2)
void mma_gemm_qkv(const fp16* __restrict__ Xq, const fp16* __restrict__ Xk,
                  const fp16* __restrict__ Xv,
                  const fp16* __restrict__ Wq, const fp16* __restrict__ Wk,
                  const fp16* __restrict__ Wv,
                  const float* __restrict__ bq, const float* __restrict__ bk,
                  const float* __restrict__ bv,
                  fp16* __restrict__ Q, fp16* __restrict__ K,
                  fp16* __restrict__ V)
{
    const fp16 *A, *W; const float* bi; fp16* O;
    if (blockIdx.z == 0)      { A = Xq; W = Wq; bi = bq; O = Q; }
    else if (blockIdx.z == 1) { A = Xk; W = Wk; bi = bk; O = K; }
    else                      { A = Xv; W = Wv; bi = bv; O = V; }
    gemm_core<1>(A, W, bi, nullptr, O, B_ * S_, D_, D_,
                 blockIdx.y * 128, blockIdx.x * 128);
}

// ---------------------------------------------------------------------------
// Prep: round three fp32 tensors -> fp16 (one launch for X's, one for W's)
// ---------------------------------------------------------------------------
__global__ __launch_bounds__(256)
void round3_kernel(const float4* __restrict__ a, const float4* __restrict__ b,
                   const float4* __restrict__ c,
                   uint2* __restrict__ oa, uint2* __restrict__ ob,
                   uint2* __restrict__ oc, int blk_per)
{
    int bb = blockIdx.x;
    const float4* src; uint2* dst;
    if (bb < blk_per)            { src = a; dst = oa; }
    else if (bb < 2 * blk_per)   { src = b; dst = ob; bb -= blk_per; }
    else                         { src = c; dst = oc; bb -= 2 * blk_per; }
    int i = bb * 256 + threadIdx.x;
    float4 x = src[i];
    __align__(8) fp16 h[4];
    h[0] = __float2half_rn(x.x); h[1] = __float2half_rn(x.y);
    h[2] = __float2half_rn(x.z); h[3] = __float2half_rn(x.w);
    dst[i] = *(uint2*)h;
}
#define XBLK (B_ * S_ * D_ / 4 / 256)      // 16384
#define WBLK (D_ * D_ / 4 / 256)           // 1024

// ---------------------------------------------------------------------------
// per-batch transpose of V: [B][S][D] -> [B][D][S]
// ---------------------------------------------------------------------------
__global__ __launch_bounds__(256)
void transpose_kernel(const fp16* __restrict__ src, fp16* __restrict__ dst)
{
    __shared__ fp16 t[32][33];
    const int b = blockIdx.z;
    const int x0 = blockIdx.x * 32;   // D dim
    const int y0 = blockIdx.y * 32;   // S dim
    const int tx = threadIdx.x & 31;
    const int ty = threadIdx.x >> 5;  // 0..7
    const fp16* s = src + (size_t)b * S_ * D_;
    fp16* d = dst + (size_t)b * S_ * D_;
#pragma unroll
    for (int j = 0; j < 4; j++) {
        int r = ty + j * 8;
        t[r][tx] = s[(size_t)(y0 + r) * D_ + x0 + tx];
    }
    __syncthreads();
#pragma unroll
    for (int j = 0; j < 4; j++) {
        int r = ty + j * 8;
        d[(size_t)(x0 + r) * S_ + y0 + tx] = t[tx][r];
    }
}

// ---------------------------------------------------------------------------
// Masked softmax, in place on fp16 buffer: raw fp16 scores -> fp16 probs.
// Applies 1/sqrt(D) scale. Whole row held in registers, so in-place is safe.
// ---------------------------------------------------------------------------
__global__ __launch_bounds__(256)
void softmax_kernel(fp16* __restrict__ P, const int* __restrict__ mask)
{
    const int row = blockIdx.x;               // 0..B*S-1
    const int b   = row / S_;
    fp16* p = P + (long long)row * S_;
    const int* mrow = mask + (long long)b * S_;

    const int tid = threadIdx.x;
    const int c0 = tid * 8;
    const float sc = 1.0f / 32.0f;            // 1/sqrt(1024)

    uint4 raw = *(const uint4*)&p[c0];        // 8 halves
    __half2* hp = (__half2*)&raw;
    int4 m0 = *(const int4*)&mrow[c0];
    int4 m1 = *(const int4*)&mrow[c0 + 4];

    float v[8];
#pragma unroll
    for (int i = 0; i < 4; i++) {
        float2 f = __half22float2(hp[i]);
        v[i * 2]     = f.x * sc;
        v[i * 2 + 1] = f.y * sc;
    }
    int mk[8] = {m0.x, m0.y, m0.z, m0.w, m1.x, m1.y, m1.z, m1.w};

    float mx = -CUDART_INF_F;
#pragma unroll
    for (int i = 0; i < 8; i++)
        if (mk[i]) mx = fmaxf(mx, v[i]);
#pragma unroll
    for (int o = 16; o > 0; o >>= 1)
        mx = fmaxf(mx, __shfl_xor_sync(0xFFFFFFFFu, mx, o));

    __shared__ float sred[8];
    if ((tid & 31) == 0) sred[tid >> 5] = mx;
    __syncthreads();
    mx = sred[0];
#pragma unroll
    for (int w = 1; w < 8; w++) mx = fmaxf(mx, sred[w]);
    __syncthreads();

    const float mxs = (mx > -CUDART_INF_F) ? mx : 0.f;

    float sum = 0.f;
#pragma unroll
    for (int i = 0; i < 8; i++) {
        float e = mk[i] ? __expf(v[i] - mxs) : 0.f;
        v[i] = e;
        sum += e;
    }
#pragma unroll
    for (int o = 16; o > 0; o >>= 1)
        sum += __shfl_xor_sync(0xFFFFFFFFu, sum, o);
    if ((tid & 31) == 0) sred[tid >> 5] = sum;
    __syncthreads();
    sum = 0.f;
#pragma unroll
    for (int w = 0; w < 8; w++) sum += sred[w];

    const float inv = (sum > 0.f) ? (1.f / sum) : 0.f;

    __align__(16) fp16 hh[8];
#pragma unroll
    for (int i = 0; i < 8; i++)
        hh[i] = __float2half_rn(v[i] * inv);
    *(uint4*)&p[c0] = *(uint4*)hh;
}

// ---------------------------------------------------------------------------
// Launch
// ---------------------------------------------------------------------------
extern "C" void kernel_launch(void* const* d_in, const int* in_sizes, int n_in,
                              void* d_out, int out_size)
{
    const float* query = (const float*)d_in[0];
    const float* key   = (const float*)d_in[1];
    const float* value = (const float*)d_in[2];
    const int*   mask  = (const int*)  d_in[3];
    const float* Wq    = (const float*)d_in[4];
    const float* bq    = (const float*)d_in[5];
    const float* Wk    = (const float*)d_in[6];
    const float* bk    = (const float*)d_in[7];
    const float* Wv    = (const float*)d_in[8];
    const float* bv    = (const float*)d_in[9];
    float* out = (float*)d_out;

    fp16 *Xq, *Xk, *Xv, *Wqh, *Wkh, *Wvh;
    fp16 *Q, *K, *V, *Vt, *P;
    cudaGetSymbolAddress((void**)&Xq,  gXq);
    cudaGetSymbolAddress((void**)&Xk,  gXk);
    cudaGetSymbolAddress((void**)&Xv,  gXv);
    cudaGetSymbolAddress((void**)&Wqh, gWq);
    cudaGetSymbolAddress((void**)&Wkh, gWk);
    cudaGetSymbolAddress((void**)&Wvh, gWv);
    cudaGetSymbolAddress((void**)&Q,   gQ);
    cudaGetSymbolAddress((void**)&K,   gK);
    cudaGetSymbolAddress((void**)&V,   gV);
    cudaGetSymbolAddress((void**)&Vt,  gVt);
    cudaGetSymbolAddress((void**)&P,   gP);

    cudaFuncSetAttribute(mma_gemm<0>, cudaFuncAttributeMaxDynamicSharedMemorySize, SMEM_DYN);
    cudaFuncSetAttribute(mma_gemm<2>, cudaFuncAttributeMaxDynamicSharedMemorySize, SMEM_DYN);
    cudaFuncSetAttribute(mma_gemm_qkv, cudaFuncAttributeMaxDynamicSharedMemorySize, SMEM_DYN);

    const int M = B_ * S_;                  // 16384

    // launch 0: round X inputs to fp16
    round3_kernel<<<3 * XBLK, 256>>>((const float4*)query, (const float4*)key,
                                     (const float4*)value,
                                     (uint2*)Xq, (uint2*)Xk, (uint2*)Xv, XBLK);
    // launch 1: round weights to fp16
    round3_kernel<<<3 * WBLK, 256>>>((const float4*)Wq, (const float4*)Wk,
                                     (const float4*)Wv,
                                     (uint2*)Wqh, (uint2*)Wkh, (uint2*)Wvh, WBLK);

    // launch 2: fused QKV projections (fp16 out, bias in epilogue)
    {
        dim3 g(D_ / 128, M / 128, 3);       // (8, 128, 3)
        mma_gemm_qkv<<<g, NTHREADS, SMEM_DYN>>>(Xq, Xk, Xv, Wqh, Wkh, Wvh,
                                                bq, bk, bv, Q, K, V);
    }

    // launch 3: scores = Q K^T per batch, raw fp16 out into P buffer
    {
        dim3 g(S_ / 128, S_ / 128, B_);     // (16, 16, 8)
        mma_gemm<2><<<g, NTHREADS, SMEM_DYN>>>(Q, K, nullptr, nullptr, P,
                                               S_, S_, D_,
                                               (long long)S_ * D_, (long long)S_ * D_,
                                               (long long)S_ * S_);
    }

    // launch 4: transpose V per batch: [S,D] -> [D,S]
    {
        dim3 g(D_ / 32, S_ / 32, B_);
        transpose_kernel<<<g, 256>>>(V, Vt);
    }

    // launch 5: masked softmax in place (applies 1/sqrt(D))
    softmax_kernel<<<B_ * S_, 256>>>(P, mask);

    // launch 6: out = P V per batch (NT with V^T), fp32 out
    {
        dim3 g(D_ / 128, S_ / 128, B_);     // (8, 16, 8)
        mma_gemm<0><<<g, NTHREADS, SMEM_DYN>>>(P, Vt, nullptr, out, nullptr,
                                               S_, D_, S_,
                                               (long long)S_ * S_, (long long)S_ * D_,
                                               (long long)S_ * D_);
    }
}

// round 16
// speedup vs baseline: 1.1017x; 1.0027x over previous
#include <cuda_runtime.h>
#include <cuda_fp16.h>
#include <math_constants.h>
#include <cstdint>

// ---------------------------------------------------------------------------
// Problem constants
// ---------------------------------------------------------------------------
#define B_ 8
#define S_ 2048
#define D_ 1024

typedef __half fp16;

// ---------------------------------------------------------------------------
// Scratch (device globals; allocation-free rule)
// ---------------------------------------------------------------------------
__device__ fp16 gXq[B_*S_*D_], gXk[B_*S_*D_], gXv[B_*S_*D_];
__device__ fp16 gWq[D_*D_], gWk[D_*D_], gWv[D_*D_];
__device__ fp16 gQ[B_*S_*D_], gK[B_*S_*D_], gV[B_*S_*D_];
__device__ fp16 gVt[B_*S_*D_];                // [B][D][S]
__device__ fp16 gP[(long long)B_*S_*S_];      // unnormalized exp(scores)
__device__ float gSum[B_*S_];                 // per-row exp sums

// ---------------------------------------------------------------------------
// PTX helpers (sm_80-baseline: cp.async, ldmatrix, mma.sync)
// ---------------------------------------------------------------------------
__device__ __forceinline__ uint32_t smem_u32(const void* p) {
    uint32_t a;
    asm("{ .reg .u64 t; cvta.to.shared.u64 t, %1; cvt.u32.u64 %0, t; }" : "=r"(a) : "l"(p));
    return a;
}
__device__ __forceinline__ void cp16(uint32_t dst, const void* src) {
    asm volatile("cp.async.cg.shared.global [%0], [%1], 16;"
                 :: "r"(dst), "l"(__cvta_generic_to_global(src)) : "memory");
}
#define CP_COMMIT() asm volatile("cp.async.commit_group;" ::: "memory")
#define CP_WAIT(n)  asm volatile("cp.async.wait_group %0;" :: "n"(n) : "memory")

__device__ __forceinline__ void ldm_x4(uint32_t* r, uint32_t addr) {
    asm volatile("ldmatrix.sync.aligned.m8n8.x4.shared.b16 {%0,%1,%2,%3}, [%4];"
                 : "=r"(r[0]), "=r"(r[1]), "=r"(r[2]), "=r"(r[3]) : "r"(addr));
}
__device__ __forceinline__ void mma_fp16(float* d, const uint32_t* a, const uint32_t* b) {
    asm volatile("mma.sync.aligned.m16n8k16.row.col.f32.f16.f16.f32 "
                 "{%0,%1,%2,%3}, {%4,%5,%6,%7}, {%8,%9}, {%0,%1,%2,%3};"
                 : "+f"(d[0]), "+f"(d[1]), "+f"(d[2]), "+f"(d[3])
                 : "r"(a[0]), "r"(a[1]), "r"(a[2]), "r"(a[3]), "r"(b[0]), "r"(b[1]));
}

// ---------------------------------------------------------------------------
// GEMM core: C[M,N] = A[M,K] * B[N,K]^T, single-pass fp16, mma.sync
// CTA tile 128x128, BK=32, 4 warps (2m x 2n, each 64x64), 5-stage cp.async,
// register-level fragment double buffering.  2 CTAs/SM.
// EPI==1: fp16 store of acc+bias (projections).
// EPI==3: masked exp(acc/32) fp16 store + row-sum atomics (scores).
// EPI==4: fp32 store of acc * inv(rowsum) (PV).
// ---------------------------------------------------------------------------
#define BK_ 32
#define ROWB 80
#define MATB (128 * ROWB)          // 10240
#define STAGEB (2 * MATB)          // 20480 (A, B)
#define NSTAGE 5
#define SMEM_DYN (NSTAGE * STAGEB) // 102400 -> 2 CTAs/SM
#define NTHREADS 128

struct Frag {
    uint32_t a[4][4];
    uint32_t b[8][2];
};

__device__ __forceinline__ void load_stage(uint32_t sbase, int slot, int tid,
                                           const fp16* A, const fp16* Bm,
                                           int bm, int bn, int K, int k0)
{
    uint32_t sb = sbase + (uint32_t)slot * STAGEB;
#pragma unroll
    for (int t = 0; t < 4; t++) {
        int u = tid + NTHREADS * t;         // 0..511
        int row = u >> 2;                   // 0..127
        int c = (u & 3) * 16;               // byte offset within 64B row
        uint32_t so = (uint32_t)(row * ROWB + c);
        size_t gA = (size_t)(bm + row) * K + k0 + (c >> 1);
        size_t gB = (size_t)(bn + row) * K + k0 + (c >> 1);
        cp16(sb + so,        A  + gA);
        cp16(sb + MATB + so, Bm + gB);
    }
    CP_COMMIT();
}

__device__ __forceinline__ void load_frags(Frag& f, uint32_t st, int kb,
                                           int wm, int wn,
                                           int a_row, int a_k16,
                                           int b_row, int b_k16)
{
#pragma unroll
    for (int mf = 0; mf < 4; mf++) {
        uint32_t ra = st + (uint32_t)((wm + mf * 16 + a_row) * ROWB + kb + a_k16);
        ldm_x4(f.a[mf], ra);
    }
#pragma unroll
    for (int np = 0; np < 4; np++) {
        uint32_t rb = st + MATB +
                      (uint32_t)((wn + np * 16 + b_row) * ROWB + kb + b_k16);
        uint32_t th[4];
        ldm_x4(th, rb);
        f.b[np*2][0]   = th[0]; f.b[np*2][1]   = th[1];
        f.b[np*2+1][0] = th[2]; f.b[np*2+1][1] = th[3];
    }
}

__device__ __forceinline__ void run_mmas(float acc[4][8][4], const Frag& f)
{
#pragma unroll
    for (int mf = 0; mf < 4; mf++)
#pragma unroll
        for (int nf = 0; nf < 8; nf++)
            mma_fp16(acc[mf][nf], f.a[mf], f.b[nf]);
}

template <int EPI>
__device__ __forceinline__ void gemm_core(
    const fp16* __restrict__ A, const fp16* __restrict__ Bm,
    const float* __restrict__ bias,
    float* __restrict__ Cf, fp16* __restrict__ Ch,
    int M, int N, int K, int bm, int bn,
    const int* __restrict__ maskRow,   // EPI==3: mask for this batch [N]
    float* __restrict__ sums)          // EPI==3/4: per-row sums for this batch [M]
{
    extern __shared__ char smem[];
    const int tid  = threadIdx.x;
    const int wid  = tid >> 5;              // 0..3
    const int lane = tid & 31;

    const int wm = (wid >> 1) * 64;
    const int wn = (wid & 1) * 64;

    const uint32_t sbase = smem_u32(smem);

    float acc[4][8][4];
#pragma unroll
    for (int i = 0; i < 4; i++)
#pragma unroll
        for (int j = 0; j < 8; j++)
#pragma unroll
            for (int q = 0; q < 4; q++) acc[i][j][q] = 0.f;

    const int NITER = K / BK_;

    load_stage(sbase, 0, tid, A, Bm, bm, bn, K, 0);
    load_stage(sbase, 1, tid, A, Bm, bm, bn, K, BK_);
    load_stage(sbase, 2, tid, A, Bm, bm, bn, K, 2 * BK_);
    load_stage(sbase, 3, tid, A, Bm, bm, bn, K, 3 * BK_);

    const int a_row = lane & 15;
    const int a_k16 = (lane >> 4) * 16;
    const int b_row = (lane & 7) + ((lane >> 4) << 3);
    const int b_k16 = ((lane >> 3) & 1) * 16;

    Frag f0, f1;

    CP_WAIT(3);
    __syncthreads();
    load_frags(f0, sbase, 0, wm, wn, a_row, a_k16, b_row, b_k16);

    for (int i = 0; i < NITER; i++) {
        uint32_t st = sbase + (uint32_t)(i % NSTAGE) * STAGEB;

        load_frags(f1, st, 32, wm, wn, a_row, a_k16, b_row, b_k16);
        run_mmas(acc, f0);

        if (i + 4 < NITER)
            load_stage(sbase, (i + 4) % NSTAGE, tid, A, Bm, bm, bn, K, (i + 4) * BK_);

        if (i + 1 < NITER) {
            if (i + 5 <= NITER)      CP_WAIT(3);
            else if (i + 4 == NITER) CP_WAIT(2);
            else if (i + 3 == NITER) CP_WAIT(1);
            else                     CP_WAIT(0);
            __syncthreads();
            uint32_t stn = sbase + (uint32_t)((i + 1) % NSTAGE) * STAGEB;
            load_frags(f0, stn, 0, wm, wn, a_row, a_k16, b_row, b_k16);
        }

        run_mmas(acc, f1);
    }

    // ---- epilogue ----
    const int rr = lane >> 2;
    const int cc = (lane & 3) * 2;
    const float sc = 1.0f / 32.0f;          // 1/sqrt(1024)

    if (EPI == 3) {
        // masked exp + fp16 store + row sums
        float rsum[4][2];
#pragma unroll
        for (int mf = 0; mf < 4; mf++) { rsum[mf][0] = 0.f; rsum[mf][1] = 0.f; }
#pragma unroll
        for (int mf = 0; mf < 4; mf++) {
#pragma unroll
            for (int nf = 0; nf < 8; nf++) {
                const int row = bm + wm + mf * 16 + rr;
                const int col = bn + wn + nf * 8 + cc;
                float* a4 = acc[mf][nf];
                const bool k0 = maskRow[col] != 0;
                const bool k1 = maskRow[col + 1] != 0;
                float e0 = k0 ? __expf(a4[0] * sc) : 0.f;
                float e1 = k1 ? __expf(a4[1] * sc) : 0.f;
                float e2 = k0 ? __expf(a4[2] * sc) : 0.f;
                float e3 = k1 ? __expf(a4[3] * sc) : 0.f;
                __half2 p0; p0.x = __float2half_rn(e0); p0.y = __float2half_rn(e1);
                __half2 p1; p1.x = __float2half_rn(e2); p1.y = __float2half_rn(e3);
                *(__half2*)&Ch[(size_t)row * N + col]       = p0;
                *(__half2*)&Ch[(size_t)(row + 8) * N + col] = p1;
                rsum[mf][0] += e0 + e1;
                rsum[mf][1] += e2 + e3;
            }
        }
        // reduce over the 4 lanes sharing each row (lane&3), then atomicAdd
#pragma unroll
        for (int mf = 0; mf < 4; mf++) {
#pragma unroll
            for (int h = 0; h < 2; h++) {
                float s = rsum[mf][h];
                s += __shfl_xor_sync(0xFFFFFFFFu, s, 1);
                s += __shfl_xor_sync(0xFFFFFFFFu, s, 2);
                if ((lane & 3) == 0)
                    atomicAdd(&sums[bm + wm + mf * 16 + rr + h * 8], s);
            }
        }
    } else {
#pragma unroll
        for (int mf = 0; mf < 4; mf++) {
            float inv0 = 0.f, inv1 = 0.f;
            if (EPI == 4) {
                const int r0 = bm + wm + mf * 16 + rr;
                float s0 = sums[r0], s1 = sums[r0 + 8];
                inv0 = (s0 > 0.f) ? (1.f / s0) : 0.f;
                inv1 = (s1 > 0.f) ? (1.f / s1) : 0.f;
            }
#pragma unroll
            for (int nf = 0; nf < 8; nf++) {
                const int row = bm + wm + mf * 16 + rr;
                const int col = bn + wn + nf * 8 + cc;
                float* a4 = acc[mf][nf];
                if (EPI == 4) {
                    *(float2*)&Cf[(size_t)row * N + col]       = make_float2(a4[0] * inv0, a4[1] * inv0);
                    *(float2*)&Cf[(size_t)(row + 8) * N + col] = make_float2(a4[2] * inv1, a4[3] * inv1);
                } else {
                    const float b0 = bias[col], b1 = bias[col + 1];
                    __half2 p0; p0.x = __float2half_rn(a4[0] + b0); p0.y = __float2half_rn(a4[1] + b1);
                    __half2 p1; p1.x = __float2half_rn(a4[2] + b0); p1.y = __float2half_rn(a4[3] + b1);
                    *(__half2*)&Ch[(size_t)row * N + col]       = p0;
                    *(__half2*)&Ch[(size_t)(row + 8) * N + col] = p1;
                }
            }
        }
    }
}

// ---------------------------------------------------------------------------
// Kernel wrappers
// ---------------------------------------------------------------------------
// fused QKV projections: blockIdx.z selects which projection
__global__ __launch_bounds__(NTHREADS, 2)
void mma_gemm_qkv(const fp16* __restrict__ Xq, const fp16* __restrict__ Xk,
                  const fp16* __restrict__ Xv,
                  const fp16* __restrict__ Wq, const fp16* __restrict__ Wk,
                  const fp16* __restrict__ Wv,
                  const float* __restrict__ bq, const float* __restrict__ bk,
                  const float* __restrict__ bv,
                  fp16* __restrict__ Q, fp16* __restrict__ K,
                  fp16* __restrict__ V)
{
    const fp16 *A, *W; const float* bi; fp16* O;
    if (blockIdx.z == 0)      { A = Xq; W = Wq; bi = bq; O = Q; }
    else if (blockIdx.z == 1) { A = Xk; W = Wk; bi = bk; O = K; }
    else                      { A = Xv; W = Wv; bi = bv; O = V; }
    gemm_core<1>(A, W, bi, nullptr, O, B_ * S_, D_, D_,
                 blockIdx.y * 128, blockIdx.x * 128, nullptr, nullptr);
}

// scores: exp(QK^T/32) masked, fp16 out + row sums
__global__ __launch_bounds__(NTHREADS, 2)
void mma_gemm_scores(const fp16* __restrict__ Q, const fp16* __restrict__ K,
                     fp16* __restrict__ P, const int* __restrict__ mask,
                     float* __restrict__ sums)
{
    const long long bz = blockIdx.z;
    gemm_core<3>(Q + bz * S_ * D_, K + bz * S_ * D_, nullptr,
                 nullptr, P + bz * (long long)S_ * S_,
                 S_, S_, D_, blockIdx.y * 128, blockIdx.x * 128,
                 mask + bz * S_, sums + bz * S_);
}

// PV: out = (P Vt^T) * inv(rowsum), fp32 out
__global__ __launch_bounds__(NTHREADS, 2)
void mma_gemm_pv(const fp16* __restrict__ P, const fp16* __restrict__ Vt,
                 float* __restrict__ out, const float* __restrict__ sums)
{
    const long long bz = blockIdx.z;
    gemm_core<4>(P + bz * (long long)S_ * S_, Vt + bz * S_ * D_, nullptr,
                 out + bz * (long long)S_ * D_, nullptr,
                 S_, D_, S_, blockIdx.y * 128, blockIdx.x * 128,
                 nullptr, const_cast<float*>(sums) + bz * S_);
}

// ---------------------------------------------------------------------------
// Prep: round three fp32 tensors -> fp16 (one launch for X's, one for W's)
// ---------------------------------------------------------------------------
__global__ __launch_bounds__(256)
void round3_kernel(const float4* __restrict__ a, const float4* __restrict__ b,
                   const float4* __restrict__ c,
                   uint2* __restrict__ oa, uint2* __restrict__ ob,
                   uint2* __restrict__ oc, int blk_per)
{
    int bb = blockIdx.x;
    const float4* src; uint2* dst;
    if (bb < blk_per)            { src = a; dst = oa; }
    else if (bb < 2 * blk_per)   { src = b; dst = ob; bb -= blk_per; }
    else                         { src = c; dst = oc; bb -= 2 * blk_per; }
    int i = bb * 256 + threadIdx.x;
    float4 x = src[i];
    __align__(8) fp16 h[4];
    h[0] = __float2half_rn(x.x); h[1] = __float2half_rn(x.y);
    h[2] = __float2half_rn(x.z); h[3] = __float2half_rn(x.w);
    dst[i] = *(uint2*)h;
}
#define XBLK (B_ * S_ * D_ / 4 / 256)      // 16384
#define WBLK (D_ * D_ / 4 / 256)           // 1024

__global__ __launch_bounds__(256)
void zero_sums_kernel(float* __restrict__ sums)
{
    sums[blockIdx.x * 256 + threadIdx.x] = 0.f;
}

// ---------------------------------------------------------------------------
// per-batch transpose of V: [B][S][D] -> [B][D][S]
// ---------------------------------------------------------------------------
__global__ __launch_bounds__(256)
void transpose_kernel(const fp16* __restrict__ src, fp16* __restrict__ dst)
{
    __shared__ fp16 t[32][33];
    const int b = blockIdx.z;
    const int x0 = blockIdx.x * 32;   // D dim
    const int y0 = blockIdx.y * 32;   // S dim
    const int tx = threadIdx.x & 31;
    const int ty = threadIdx.x >> 5;  // 0..7
    const fp16* s = src + (size_t)b * S_ * D_;
    fp16* d = dst + (size_t)b * S_ * D_;
#pragma unroll
    for (int j = 0; j < 4; j++) {
        int r = ty + j * 8;
        t[r][tx] = s[(size_t)(y0 + r) * D_ + x0 + tx];
    }
    __syncthreads();
#pragma unroll
    for (int j = 0; j < 4; j++) {
        int r = ty + j * 8;
        d[(size_t)(x0 + r) * S_ + y0 + tx] = t[tx][r];
    }
}

// ---------------------------------------------------------------------------
// Launch
// ---------------------------------------------------------------------------
extern "C" void kernel_launch(void* const* d_in, const int* in_sizes, int n_in,
                              void* d_out, int out_size)
{
    const float* query = (const float*)d_in[0];
    const float* key   = (const float*)d_in[1];
    const float* value = (const float*)d_in[2];
    const int*   mask  = (const int*)  d_in[3];
    const float* Wq    = (const float*)d_in[4];
    const float* bq    = (const float*)d_in[5];
    const float* Wk    = (const float*)d_in[6];
    const float* bk    = (const float*)d_in[7];
    const float* Wv    = (const float*)d_in[8];
    const float* bv    = (const float*)d_in[9];
    float* out = (float*)d_out;

    fp16 *Xq, *Xk, *Xv, *Wqh, *Wkh, *Wvh;
    fp16 *Q, *K, *V, *Vt, *P;
    float* Sum;
    cudaGetSymbolAddress((void**)&Xq,  gXq);
    cudaGetSymbolAddress((void**)&Xk,  gXk);
    cudaGetSymbolAddress((void**)&Xv,  gXv);
    cudaGetSymbolAddress((void**)&Wqh, gWq);
    cudaGetSymbolAddress((void**)&Wkh, gWk);
    cudaGetSymbolAddress((void**)&Wvh, gWv);
    cudaGetSymbolAddress((void**)&Q,   gQ);
    cudaGetSymbolAddress((void**)&K,   gK);
    cudaGetSymbolAddress((void**)&V,   gV);
    cudaGetSymbolAddress((void**)&Vt,  gVt);
    cudaGetSymbolAddress((void**)&P,   gP);
    cudaGetSymbolAddress((void**)&Sum, gSum);

    cudaFuncSetAttribute(mma_gemm_qkv,    cudaFuncAttributeMaxDynamicSharedMemorySize, SMEM_DYN);
    cudaFuncSetAttribute(mma_gemm_scores, cudaFuncAttributeMaxDynamicSharedMemorySize, SMEM_DYN);
    cudaFuncSetAttribute(mma_gemm_pv,     cudaFuncAttributeMaxDynamicSharedMemorySize, SMEM_DYN);

    const int M = B_ * S_;                  // 16384

    // round inputs + weights to fp16; zero row-sum buffer
    round3_kernel<<<3 * XBLK, 256>>>((const float4*)query, (const float4*)key,
                                     (const float4*)value,
                                     (uint2*)Xq, (uint2*)Xk, (uint2*)Xv, XBLK);
    round3_kernel<<<3 * WBLK, 256>>>((const float4*)Wq, (const float4*)Wk,
                                     (const float4*)Wv,
                                     (uint2*)Wqh, (uint2*)Wkh, (uint2*)Wvh, WBLK);
    zero_sums_kernel<<<B_ * S_ / 256, 256>>>(Sum);

    // fused QKV projections
    {
        dim3 g(D_ / 128, M / 128, 3);       // (8, 128, 3)
        mma_gemm_qkv<<<g, NTHREADS, SMEM_DYN>>>(Xq, Xk, Xv, Wqh, Wkh, Wvh,
                                                bq, bk, bv, Q, K, V);
    }

    // scores: masked exp(QK^T/32) -> fp16 P + row sums
    {
        dim3 g(S_ / 128, S_ / 128, B_);     // (16, 16, 8)
        mma_gemm_scores<<<g, NTHREADS, SMEM_DYN>>>(Q, K, P, mask, Sum);
    }

    // transpose V per batch: [S,D] -> [D,S]
    {
        dim3 g(D_ / 32, S_ / 32, B_);
        transpose_kernel<<<g, 256>>>(V, Vt);
    }

    // out = P V * inv(rowsum), fp32
    {
        dim3 g(D_ / 128, S_ / 128, B_);     // (8, 16, 8)
        mma_gemm_pv<<<g, NTHREADS, SMEM_DYN>>>(P, Vt, out, Sum);
    }
}

// round 17
// speedup vs baseline: 1.2033x; 1.0922x over previous
#include <cuda_runtime.h>
#include <cuda_fp16.h>
#include <math_constants.h>
#include <cstdint>

// ---------------------------------------------------------------------------
// Problem constants
// ---------------------------------------------------------------------------
#define B_ 8
#define S_ 2048
#define D_ 1024

typedef __half fp16;

// ---------------------------------------------------------------------------
// Scratch (device globals; allocation-free rule)
// ---------------------------------------------------------------------------
__device__ fp16 gXq[B_*S_*D_], gXk[B_*S_*D_], gXv[B_*S_*D_];
__device__ fp16 gWq[D_*D_], gWk[D_*D_], gWv[D_*D_];
__device__ fp16 gQ[B_*S_*D_], gK[B_*S_*D_], gV[B_*S_*D_];
__device__ fp16 gVt[B_*S_*D_];                // [B][D][S]
__device__ fp16 gP[(long long)B_*S_*S_];      // unnormalized exp(scores)
__device__ float gSum[B_*S_];                 // per-row exp sums

// ---------------------------------------------------------------------------
// PTX helpers (sm_80-baseline: cp.async, ldmatrix, mma.sync)
// ---------------------------------------------------------------------------
__device__ __forceinline__ uint32_t smem_u32(const void* p) {
    uint32_t a;
    asm("{ .reg .u64 t; cvta.to.shared.u64 t, %1; cvt.u32.u64 %0, t; }" : "=r"(a) : "l"(p));
    return a;
}
__device__ __forceinline__ void cp16(uint32_t dst, const void* src) {
    asm volatile("cp.async.cg.shared.global [%0], [%1], 16;"
                 :: "r"(dst), "l"(__cvta_generic_to_global(src)) : "memory");
}
#define CP_COMMIT() asm volatile("cp.async.commit_group;" ::: "memory")
#define CP_WAIT(n)  asm volatile("cp.async.wait_group %0;" :: "n"(n) : "memory")

__device__ __forceinline__ void ldm_x4(uint32_t* r, uint32_t addr) {
    asm volatile("ldmatrix.sync.aligned.m8n8.x4.shared.b16 {%0,%1,%2,%3}, [%4];"
                 : "=r"(r[0]), "=r"(r[1]), "=r"(r[2]), "=r"(r[3]) : "r"(addr));
}
__device__ __forceinline__ void mma_fp16(float* d, const uint32_t* a, const uint32_t* b) {
    asm volatile("mma.sync.aligned.m16n8k16.row.col.f32.f16.f16.f32 "
                 "{%0,%1,%2,%3}, {%4,%5,%6,%7}, {%8,%9}, {%0,%1,%2,%3};"
                 : "+f"(d[0]), "+f"(d[1]), "+f"(d[2]), "+f"(d[3])
                 : "r"(a[0]), "r"(a[1]), "r"(a[2]), "r"(a[3]), "r"(b[0]), "r"(b[1]));
}

// ---------------------------------------------------------------------------
// GEMM core: C[M,N] = A[M,K] * B[N,K]^T, single-pass fp16, mma.sync
// CTA tile 128x128, BK=64, 4 warps (2m x 2n, each 64x64), 3-stage cp.async,
// register fragment double buffering, ONE barrier per 64-K iteration.
// SMEM rows: 64 fp16 = 128B data at 144B stride (9r mod 8 -> conflict-free).
// EPI==1: fp16 store of acc+bias (projections).
// EPI==3: masked exp(acc/32) fp16 store + row-sum atomics (scores).
// EPI==4: fp32 store of acc * inv(rowsum) (PV).
// ---------------------------------------------------------------------------
#define BK_ 64
#define ROWB 144
#define MATB (128 * ROWB)          // 18432
#define STAGEB (2 * MATB)          // 36864 (A, B)
#define NSTAGE 3
#define SMEM_DYN (NSTAGE * STAGEB) // 110592 -> 2 CTAs/SM (216KB/SM)
#define NTHREADS 128

struct Frag {
    uint32_t a[4][4];
    uint32_t b[8][2];
};

__device__ __forceinline__ void load_stage(uint32_t sbase, int slot, int tid,
                                           const fp16* A, const fp16* Bm,
                                           int bm, int bn, int K, int k0)
{
    uint32_t sb = sbase + (uint32_t)slot * STAGEB;
#pragma unroll
    for (int t = 0; t < 8; t++) {
        int u = tid + NTHREADS * t;         // 0..1023
        int row = u >> 3;                   // 0..127
        int c = (u & 7) * 16;               // byte offset within 128B row
        uint32_t so = (uint32_t)(row * ROWB + c);
        size_t gA = (size_t)(bm + row) * K + k0 + (c >> 1);
        size_t gB = (size_t)(bn + row) * K + k0 + (c >> 1);
        cp16(sb + so,        A  + gA);
        cp16(sb + MATB + so, Bm + gB);
    }
    CP_COMMIT();
}

__device__ __forceinline__ void load_frags(Frag& f, uint32_t st, int kb,
                                           int wm, int wn,
                                           int a_row, int a_k16,
                                           int b_row, int b_k16)
{
#pragma unroll
    for (int mf = 0; mf < 4; mf++) {
        uint32_t ra = st + (uint32_t)((wm + mf * 16 + a_row) * ROWB + kb + a_k16);
        ldm_x4(f.a[mf], ra);
    }
#pragma unroll
    for (int np = 0; np < 4; np++) {
        uint32_t rb = st + MATB +
                      (uint32_t)((wn + np * 16 + b_row) * ROWB + kb + b_k16);
        uint32_t th[4];
        ldm_x4(th, rb);
        f.b[np*2][0]   = th[0]; f.b[np*2][1]   = th[1];
        f.b[np*2+1][0] = th[2]; f.b[np*2+1][1] = th[3];
    }
}

__device__ __forceinline__ void run_mmas(float acc[4][8][4], const Frag& f)
{
#pragma unroll
    for (int mf = 0; mf < 4; mf++)
#pragma unroll
        for (int nf = 0; nf < 8; nf++)
            mma_fp16(acc[mf][nf], f.a[mf], f.b[nf]);
}

template <int EPI>
__device__ __forceinline__ void gemm_core(
    const fp16* __restrict__ A, const fp16* __restrict__ Bm,
    const float* __restrict__ bias,
    float* __restrict__ Cf, fp16* __restrict__ Ch,
    int M, int N, int K, int bm, int bn,
    const int* __restrict__ maskRow,   // EPI==3: mask for this batch [N]
    float* __restrict__ sums)          // EPI==3/4: per-row sums for this batch [M]
{
    extern __shared__ char smem[];
    const int tid  = threadIdx.x;
    const int wid  = tid >> 5;              // 0..3
    const int lane = tid & 31;

    const int wm = (wid >> 1) * 64;
    const int wn = (wid & 1) * 64;

    const uint32_t sbase = smem_u32(smem);

    float acc[4][8][4];
#pragma unroll
    for (int i = 0; i < 4; i++)
#pragma unroll
        for (int j = 0; j < 8; j++)
#pragma unroll
            for (int q = 0; q < 4; q++) acc[i][j][q] = 0.f;

    const int NITER = K / BK_;              // >= 16

    load_stage(sbase, 0, tid, A, Bm, bm, bn, K, 0);
    load_stage(sbase, 1, tid, A, Bm, bm, bn, K, BK_);

    const int a_row = lane & 15;
    const int a_k16 = (lane >> 4) * 16;
    const int b_row = (lane & 7) + ((lane >> 4) << 3);
    const int b_k16 = ((lane >> 3) & 1) * 16;

    Frag f0, f1;

    // wait stage 0 (stage 1 still in flight), preload fragments ks=0
    CP_WAIT(1);
    __syncthreads();
    load_frags(f0, sbase, 0, wm, wn, a_row, a_k16, b_row, b_k16);

    for (int i = 0; i < NITER; i++) {
        uint32_t st = sbase + (uint32_t)(i % NSTAGE) * STAGEB;

        // ks0 -> ks1 -> ks2 -> ks3, frag double-buffered
        load_frags(f1, st, 32, wm, wn, a_row, a_k16, b_row, b_k16);   // ks1
        run_mmas(acc, f0);                                            // ks0

        // issue global loads for stage i+2 (slot protected by iter i-1 barrier)
        if (i + 2 < NITER)
            load_stage(sbase, (i + 2) % NSTAGE, tid, A, Bm, bm, bn, K, (i + 2) * BK_);

        load_frags(f0, st, 64, wm, wn, a_row, a_k16, b_row, b_k16);   // ks2
        run_mmas(acc, f1);                                            // ks1
        load_frags(f1, st, 96, wm, wn, a_row, a_k16, b_row, b_k16);   // ks3
        run_mmas(acc, f0);                                            // ks2

        // make stage i+1 visible, prefetch its ks=0 fragments
        if (i + 1 < NITER) {
            if (i + 2 < NITER) CP_WAIT(1);
            else               CP_WAIT(0);
            __syncthreads();
            uint32_t stn = sbase + (uint32_t)((i + 1) % NSTAGE) * STAGEB;
            load_frags(f0, stn, 0, wm, wn, a_row, a_k16, b_row, b_k16);
        }

        run_mmas(acc, f1);                                            // ks3
    }

    // ---- epilogue ----
    const int rr = lane >> 2;
    const int cc = (lane & 3) * 2;
    const float sc = 1.0f / 32.0f;          // 1/sqrt(1024)

    if (EPI == 3) {
        // masked exp + fp16 store + row sums
        float rsum[4][2];
#pragma unroll
        for (int mf = 0; mf < 4; mf++) { rsum[mf][0] = 0.f; rsum[mf][1] = 0.f; }
#pragma unroll
        for (int mf = 0; mf < 4; mf++) {
#pragma unroll
            for (int nf = 0; nf < 8; nf++) {
                const int row = bm + wm + mf * 16 + rr;
                const int col = bn + wn + nf * 8 + cc;
                float* a4 = acc[mf][nf];
                const bool k0 = maskRow[col] != 0;
                const bool k1 = maskRow[col + 1] != 0;
                float e0 = k0 ? __expf(a4[0] * sc) : 0.f;
                float e1 = k1 ? __expf(a4[1] * sc) : 0.f;
                float e2 = k0 ? __expf(a4[2] * sc) : 0.f;
                float e3 = k1 ? __expf(a4[3] * sc) : 0.f;
                __half2 p0; p0.x = __float2half_rn(e0); p0.y = __float2half_rn(e1);
                __half2 p1; p1.x = __float2half_rn(e2); p1.y = __float2half_rn(e3);
                *(__half2*)&Ch[(size_t)row * N + col]       = p0;
                *(__half2*)&Ch[(size_t)(row + 8) * N + col] = p1;
                rsum[mf][0] += e0 + e1;
                rsum[mf][1] += e2 + e3;
            }
        }
#pragma unroll
        for (int mf = 0; mf < 4; mf++) {
#pragma unroll
            for (int h = 0; h < 2; h++) {
                float s = rsum[mf][h];
                s += __shfl_xor_sync(0xFFFFFFFFu, s, 1);
                s += __shfl_xor_sync(0xFFFFFFFFu, s, 2);
                if ((lane & 3) == 0)
                    atomicAdd(&sums[bm + wm + mf * 16 + rr + h * 8], s);
            }
        }
    } else {
#pragma unroll
        for (int mf = 0; mf < 4; mf++) {
            float inv0 = 0.f, inv1 = 0.f;
            if (EPI == 4) {
                const int r0 = bm + wm + mf * 16 + rr;
                float s0 = sums[r0], s1 = sums[r0 + 8];
                inv0 = (s0 > 0.f) ? (1.f / s0) : 0.f;
                inv1 = (s1 > 0.f) ? (1.f / s1) : 0.f;
            }
#pragma unroll
            for (int nf = 0; nf < 8; nf++) {
                const int row = bm + wm + mf * 16 + rr;
                const int col = bn + wn + nf * 8 + cc;
                float* a4 = acc[mf][nf];
                if (EPI == 4) {
                    *(float2*)&Cf[(size_t)row * N + col]       = make_float2(a4[0] * inv0, a4[1] * inv0);
                    *(float2*)&Cf[(size_t)(row + 8) * N + col] = make_float2(a4[2] * inv1, a4[3] * inv1);
                } else {
                    const float b0 = bias[col], b1 = bias[col + 1];
                    __half2 p0; p0.x = __float2half_rn(a4[0] + b0); p0.y = __float2half_rn(a4[1] + b1);
                    __half2 p1; p1.x = __float2half_rn(a4[2] + b0); p1.y = __float2half_rn(a4[3] + b1);
                    *(__half2*)&Ch[(size_t)row * N + col]       = p0;
                    *(__half2*)&Ch[(size_t)(row + 8) * N + col] = p1;
                }
            }
        }
    }
}

// ---------------------------------------------------------------------------
// Kernel wrappers
// ---------------------------------------------------------------------------
__global__ __launch_bounds__(NTHREADS, 2)
void mma_gemm_qkv(const fp16* __restrict__ Xq, const fp16* __restrict__ Xk,
                  const fp16* __restrict__ Xv,
                  const fp16* __restrict__ Wq, const fp16* __restrict__ Wk,
                  const fp16* __restrict__ Wv,
                  const float* __restrict__ bq, const float* __restrict__ bk,
                  const float* __restrict__ bv,
                  fp16* __restrict__ Q, fp16* __restrict__ K,
                  fp16* __restrict__ V)
{
    const fp16 *A, *W; const float* bi; fp16* O;
    if (blockIdx.z == 0)      { A = Xq; W = Wq; bi = bq; O = Q; }
    else if (blockIdx.z == 1) { A = Xk; W = Wk; bi = bk; O = K; }
    else                      { A = Xv; W = Wv; bi = bv; O = V; }
    gemm_core<1>(A, W, bi, nullptr, O, B_ * S_, D_, D_,
                 blockIdx.y * 128, blockIdx.x * 128, nullptr, nullptr);
}

__global__ __launch_bounds__(NTHREADS, 2)
void mma_gemm_scores(const fp16* __restrict__ Q, const fp16* __restrict__ K,
                     fp16* __restrict__ P, const int* __restrict__ mask,
                     float* __restrict__ sums)
{
    const long long bz = blockIdx.z;
    gemm_core<3>(Q + bz * S_ * D_, K + bz * S_ * D_, nullptr,
                 nullptr, P + bz * (long long)S_ * S_,
                 S_, S_, D_, blockIdx.y * 128, blockIdx.x * 128,
                 mask + bz * S_, sums + bz * S_);
}

__global__ __launch_bounds__(NTHREADS, 2)
void mma_gemm_pv(const fp16* __restrict__ P, const fp16* __restrict__ Vt,
                 float* __restrict__ out, const float* __restrict__ sums)
{
    const long long bz = blockIdx.z;
    gemm_core<4>(P + bz * (long long)S_ * S_, Vt + bz * S_ * D_, nullptr,
                 out + bz * (long long)S_ * D_, nullptr,
                 S_, D_, S_, blockIdx.y * 128, blockIdx.x * 128,
                 nullptr, const_cast<float*>(sums) + bz * S_);
}

// ---------------------------------------------------------------------------
// Prep: round three fp32 tensors -> fp16 (one launch for X's, one for W's)
// ---------------------------------------------------------------------------
__global__ __launch_bounds__(256)
void round3_kernel(const float4* __restrict__ a, const float4* __restrict__ b,
                   const float4* __restrict__ c,
                   uint2* __restrict__ oa, uint2* __restrict__ ob,
                   uint2* __restrict__ oc, int blk_per)
{
    int bb = blockIdx.x;
    const float4* src; uint2* dst;
    if (bb < blk_per)            { src = a; dst = oa; }
    else if (bb < 2 * blk_per)   { src = b; dst = ob; bb -= blk_per; }
    else                         { src = c; dst = oc; bb -= 2 * blk_per; }
    int i = bb * 256 + threadIdx.x;
    float4 x = src[i];
    __align__(8) fp16 h[4];
    h[0] = __float2half_rn(x.x); h[1] = __float2half_rn(x.y);
    h[2] = __float2half_rn(x.z); h[3] = __float2half_rn(x.w);
    dst[i] = *(uint2*)h;
}
#define XBLK (B_ * S_ * D_ / 4 / 256)      // 16384
#define WBLK (D_ * D_ / 4 / 256)           // 1024

__global__ __launch_bounds__(256)
void zero_sums_kernel(float* __restrict__ sums)
{
    sums[blockIdx.x * 256 + threadIdx.x] = 0.f;
}

// ---------------------------------------------------------------------------
// per-batch transpose of V: [B][S][D] -> [B][D][S]
// ---------------------------------------------------------------------------
__global__ __launch_bounds__(256)
void transpose_kernel(const fp16* __restrict__ src, fp16* __restrict__ dst)
{
    __shared__ fp16 t[32][33];
    const int b = blockIdx.z;
    const int x0 = blockIdx.x * 32;   // D dim
    const int y0 = blockIdx.y * 32;   // S dim
    const int tx = threadIdx.x & 31;
    const int ty = threadIdx.x >> 5;  // 0..7
    const fp16* s = src + (size_t)b * S_ * D_;
    fp16* d = dst + (size_t)b * S_ * D_;
#pragma unroll
    for (int j = 0; j < 4; j++) {
        int r = ty + j * 8;
        t[r][tx] = s[(size_t)(y0 + r) * D_ + x0 + tx];
    }
    __syncthreads();
#pragma unroll
    for (int j = 0; j < 4; j++) {
        int r = ty + j * 8;
        d[(size_t)(x0 + r) * S_ + y0 + tx] = t[tx][r];
    }
}

// ---------------------------------------------------------------------------
// Launch
// ---------------------------------------------------------------------------
extern "C" void kernel_launch(void* const* d_in, const int* in_sizes, int n_in,
                              void* d_out, int out_size)
{
    const float* query = (const float*)d_in[0];
    const float* key   = (const float*)d_in[1];
    const float* value = (const float*)d_in[2];
    const int*   mask  = (const int*)  d_in[3];
    const float* Wq    = (const float*)d_in[4];
    const float* bq    = (const float*)d_in[5];
    const float* Wk    = (const float*)d_in[6];
    const float* bk    = (const float*)d_in[7];
    const float* Wv    = (const float*)d_in[8];
    const float* bv    = (const float*)d_in[9];
    float* out = (float*)d_out;

    fp16 *Xq, *Xk, *Xv, *Wqh, *Wkh, *Wvh;
    fp16 *Q, *K, *V, *Vt, *P;
    float* Sum;
    cudaGetSymbolAddress((void**)&Xq,  gXq);
    cudaGetSymbolAddress((void**)&Xk,  gXk);
    cudaGetSymbolAddress((void**)&Xv,  gXv);
    cudaGetSymbolAddress((void**)&Wqh, gWq);
    cudaGetSymbolAddress((void**)&Wkh, gWk);
    cudaGetSymbolAddress((void**)&Wvh, gWv);
    cudaGetSymbolAddress((void**)&Q,   gQ);
    cudaGetSymbolAddress((void**)&K,   gK);
    cudaGetSymbolAddress((void**)&V,   gV);
    cudaGetSymbolAddress((void**)&Vt,  gVt);
    cudaGetSymbolAddress((void**)&P,   gP);
    cudaGetSymbolAddress((void**)&Sum, gSum);

    cudaFuncSetAttribute(mma_gemm_qkv,    cudaFuncAttributeMaxDynamicSharedMemorySize, SMEM_DYN);
    cudaFuncSetAttribute(mma_gemm_scores, cudaFuncAttributeMaxDynamicSharedMemorySize, SMEM_DYN);
    cudaFuncSetAttribute(mma_gemm_pv,     cudaFuncAttributeMaxDynamicSharedMemorySize, SMEM_DYN);

    const int M = B_ * S_;                  // 16384

    // round inputs + weights to fp16; zero row-sum buffer
    round3_kernel<<<3 * XBLK, 256>>>((const float4*)query, (const float4*)key,
                                     (const float4*)value,
                                     (uint2*)Xq, (uint2*)Xk, (uint2*)Xv, XBLK);
    round3_kernel<<<3 * WBLK, 256>>>((const float4*)Wq, (const float4*)Wk,
                                     (const float4*)Wv,
                                     (uint2*)Wqh, (uint2*)Wkh, (uint2*)Wvh, WBLK);
    zero_sums_kernel<<<B_ * S_ / 256, 256>>>(Sum);

    // fused QKV projections
    {
        dim3 g(D_ / 128, M / 128, 3);       // (8, 128, 3)
        mma_gemm_qkv<<<g, NTHREADS, SMEM_DYN>>>(Xq, Xk, Xv, Wqh, Wkh, Wvh,
                                                bq, bk, bv, Q, K, V);
    }

    // scores: masked exp(QK^T/32) -> fp16 P + row sums
    {
        dim3 g(S_ / 128, S_ / 128, B_);     // (16, 16, 8)
        mma_gemm_scores<<<g, NTHREADS, SMEM_DYN>>>(Q, K, P, mask, Sum);
    }

    // transpose V per batch: [S,D] -> [D,S]
    {
        dim3 g(D_ / 32, S_ / 32, B_);
        transpose_kernel<<<g, 256>>>(V, Vt);
    }

    // out = P V * inv(rowsum), fp32
    {
        dim3 g(D_ / 128, S_ / 128, B_);     // (8, 16, 8)
        mma_gemm_pv<<<g, NTHREADS, SMEM_DYN>>>(P, Vt, out, Sum);
    }
}